// round 6
// baseline (speedup 1.0000x reference)
#include <cuda_runtime.h>
#include <math.h>

#define IMG_H 480
#define IMG_W 640
#define NB    4
#define PS    (IMG_H * IMG_W)

__global__ void __launch_bounds__(256)
DepthOffset_kernel(const float* __restrict__ depth, float* __restrict__ out)
{
    const int x = blockIdx.x * 32 + threadIdx.x;
    const int y = blockIdx.y * 8  + threadIdx.y;
    const int b = blockIdx.z;
    if (x >= IMG_W || y >= IMG_H) return;

    const float* __restrict__ dp = depth + b * PS;

    // center value (always in range)
    const float cen = __ldg(&dp[y * IMG_W + x]);

    // 7x7 grid of |d[y+2(i-3), x+2(jj-3)] - cen|, zero-padded d
    float D[7][7];
#pragma unroll
    for (int i = 0; i < 7; i++) {
#pragma unroll
        for (int jj = 0; jj < 7; jj++) {
            int yy = y + 2 * i - 6;
            int xx = x + 2 * jj - 6;
            float v = 0.0f;
            if ((unsigned)yy < (unsigned)IMG_H && (unsigned)xx < (unsigned)IMG_W)
                v = __ldg(&dp[yy * IMG_W + xx]);
            D[i][jj] = fabsf(v - cen);
        }
    }

    float* __restrict__ op = out + (b * 18) * PS + y * IMG_W + x;

    // taps: j = 3R + C, big offset 4(R-1), 4(C-1)
#pragma unroll
    for (int j = 0; j < 9; j++) {
        const int R = j / 3;
        const int C = j % 3;

        // allowed small-offset set for this tap (compile-time constant)
        const unsigned mask =
            (j == 1 || j == 7) ? 0x92u :   // k in {1,4,7}
            (j == 3 || j == 5) ? 0x38u :   // k in {3,4,5}
                                 0x1FFu;   // all 9
        const int firstAllowed =
            (j == 1 || j == 7) ? 1 :
            (j == 3 || j == 5) ? 3 : 0;

        // argmin over allowed k, first occurrence wins (strict <)
        float best = INFINITY;
        int kb = firstAllowed;
#pragma unroll
        for (int k = 0; k < 9; k++) {
            if (!((mask >> k) & 1u)) continue;
            const int r = k / 3;
            const int c = k % 3;
            float v = D[2 * R + r][2 * C + c];
            bool p = v < best;
            best = p ? v : best;
            kb   = p ? k : kb;
        }

        // nested-padding override: if the intermediate index of this tap is
        // OOB, every allowed sample equals |0-cen| -> all tie -> first allowed k
        const int ym = y + 4 * (R - 1);
        const int xm = x + 4 * (C - 1);
        const bool mid_ok = (unsigned)ym < (unsigned)IMG_H &&
                            (unsigned)xm < (unsigned)IMG_W;
        kb = mid_ok ? kb : firstAllowed;

        // output dtype is float32: write offsets as float values
        op[j * PS]       = (float)(2 * (kb / 3 - 1));   // off_h
        op[(j + 9) * PS] = (float)(2 * (kb % 3 - 1));   // off_w
    }
}

extern "C" void kernel_launch(void* const* d_in, const int* in_sizes, int n_in,
                              void* d_out, int out_size)
{
    const float* depth = (const float*)d_in[0];
    float* out = (float*)d_out;

    dim3 block(32, 8);
    dim3 grid(IMG_W / 32, IMG_H / 8, NB);   // 20 x 60 x 4
    DepthOffset_kernel<<<grid, block>>>(depth, out);
}

// round 7
// speedup vs baseline: 1.3561x; 1.3561x over previous
#include <cuda_runtime.h>
#include <math.h>

#define IMG_H 480
#define IMG_W 640
#define NB    4
#define PS    (IMG_H * IMG_W)
#define TW    32
#define TH    8
#define HALO  6
#define TILE_W (TW + 2*HALO)   // 44
#define TILE_H (TH + 2*HALO)   // 20

// float bit patterns of -2.0f / 0.0f / +2.0f live entirely in bits [31:30]
#define FB(o)  ((o) == -2 ? 0xC0000000u : ((o) == 2 ? 0x40000000u : 0u))
// pack (off_h, off_w) for candidate k: oh in [31:30], ow in [29:28]
#define PKC(k) (FB(2*((k)/3 - 1)) | (FB(2*((k)%3 - 1)) >> 2))

// one argmin step (strict < keeps first occurrence, jnp.argmin semantics).
// fabsf folds into FSETP operand modifiers; best keeps the signed diff.
#define CAND(i, jj, k) { \
    float v = D[i][jj]; \
    bool p = fabsf(v) < fabsf(best); \
    best = p ? v : best; \
    pk   = p ? PKC(k) : pk; }

#define EDGE(R, C, FA) \
    if (!SAFE) { \
        int ym = y + 4*((R)-1), xm = x + 4*((C)-1); \
        if ((unsigned)ym >= (unsigned)IMG_H || (unsigned)xm >= (unsigned)IMG_W) \
            pk = PKC(FA); \
    }

#define STORE(j) { \
    op[(j)*PS]     = __uint_as_float(pk & 0xC0000000u); \
    op[((j)+9)*PS] = __uint_as_float((pk << 2) & 0xC0000000u); }

// full 9-candidate tap (j in {0,2,4,6,8}), k ascending
#define DO_FULL(j, R, C) { \
    float best = D[2*(R)][2*(C)]; unsigned pk = PKC(0); \
    CAND(2*(R),   2*(C)+1, 1) \
    CAND(2*(R),   2*(C)+2, 2) \
    CAND(2*(R)+1, 2*(C),   3) \
    CAND(2*(R)+1, 2*(C)+1, 4) \
    CAND(2*(R)+1, 2*(C)+2, 5) \
    CAND(2*(R)+2, 2*(C),   6) \
    CAND(2*(R)+2, 2*(C)+1, 7) \
    CAND(2*(R)+2, 2*(C)+2, 8) \
    EDGE(R, C, 0) \
    STORE(j) }

// column taps j in {1,7}: allowed k = {1,4,7}
#define DO_COL(j, R, C) { \
    float best = D[2*(R)][2*(C)+1]; unsigned pk = PKC(1); \
    CAND(2*(R)+1, 2*(C)+1, 4) \
    CAND(2*(R)+2, 2*(C)+1, 7) \
    EDGE(R, C, 1) \
    STORE(j) }

// row taps j in {3,5}: allowed k = {3,4,5}
#define DO_ROW(j, R, C) { \
    float best = D[2*(R)+1][2*(C)]; unsigned pk = PKC(3); \
    CAND(2*(R)+1, 2*(C)+1, 4) \
    CAND(2*(R)+1, 2*(C)+2, 5) \
    EDGE(R, C, 3) \
    STORE(j) }

template<bool SAFE>
__device__ __forceinline__ void compute_px(
    const float (&tile)[TILE_H][TILE_W],
    int x, int y, int cx, int cy, float* __restrict__ op)
{
    const float cen = tile[cy][cx];

    // signed diffs on the 7x7 even-offset grid:
    // D[i][jj] = d[y + 2(i-3), x + 2(jj-3)] - cen   (zero-padded d)
    float D[7][7];
#pragma unroll
    for (int i = 0; i < 7; i++)
#pragma unroll
        for (int jj = 0; jj < 7; jj++)
            D[i][jj] = tile[cy + 2*i - 6][cx + 2*jj - 6] - cen;

    DO_FULL(0, 0, 0)
    DO_COL (1, 0, 1)
    DO_FULL(2, 0, 2)
    DO_ROW (3, 1, 0)
    DO_FULL(4, 1, 1)
    DO_ROW (5, 1, 2)
    DO_FULL(6, 2, 0)
    DO_COL (7, 2, 1)
    DO_FULL(8, 2, 2)
}

__global__ void __launch_bounds__(TW * TH)
DepthOffset_kernel(const float* __restrict__ depth, float* __restrict__ out)
{
    __shared__ float tile[TILE_H][TILE_W];

    const int b   = blockIdx.z;
    const int bx0 = blockIdx.x * TW;
    const int by0 = blockIdx.y * TH;
    const int tx  = threadIdx.x, ty = threadIdx.y;
    const int t   = ty * TW + tx;

    const float* __restrict__ dp = depth + b * PS;

    // is the whole tile (incl. halo 6) inside the image?
    const bool safe = (bx0 >= HALO) && (bx0 + TW + HALO <= IMG_W) &&
                      (by0 >= HALO) && (by0 + TH + HALO <= IMG_H);

    if (safe) {
#pragma unroll
        for (int i = t; i < TILE_H * TILE_W; i += TW * TH) {
            int r = i / TILE_W;
            int c = i - r * TILE_W;
            tile[r][c] = dp[(by0 - HALO + r) * IMG_W + (bx0 - HALO + c)];
        }
    } else {
#pragma unroll
        for (int i = t; i < TILE_H * TILE_W; i += TW * TH) {
            int r  = i / TILE_W;
            int c  = i - r * TILE_W;
            int gy = by0 - HALO + r;
            int gx = bx0 - HALO + c;
            float v = 0.0f;
            if ((unsigned)gy < (unsigned)IMG_H && (unsigned)gx < (unsigned)IMG_W)
                v = dp[gy * IMG_W + gx];
            tile[r][c] = v;
        }
    }
    __syncthreads();

    const int x = bx0 + tx;
    const int y = by0 + ty;
    float* __restrict__ op = out + (b * 18) * PS + y * IMG_W + x;

    if (safe)
        compute_px<true >(tile, x, y, tx + HALO, ty + HALO, op);
    else
        compute_px<false>(tile, x, y, tx + HALO, ty + HALO, op);
}

extern "C" void kernel_launch(void* const* d_in, const int* in_sizes, int n_in,
                              void* d_out, int out_size)
{
    const float* depth = (const float*)d_in[0];
    float* out = (float*)d_out;

    dim3 block(TW, TH);
    dim3 grid(IMG_W / TW, IMG_H / TH, NB);   // 20 x 60 x 4
    DepthOffset_kernel<<<grid, block>>>(depth, out);
}